// round 1
// baseline (speedup 1.0000x reference)
#include <cuda_runtime.h>
#include <math.h>

#define HID 256
#define QN 64
#define LQ 20
#define DN 24
#define LD 50
#define QROWS (QN*LQ)   // 1280
#define DROWS (DN*LD)   // 1200

// ---------------- scratch (device globals; no allocation allowed) ----------
__device__ __align__(16) float g_xq[QROWS*HID];
__device__ __align__(16) float g_xd[DROWS*HID];
__device__ __align__(16) float g_giq[QROWS*768];
__device__ __align__(16) float g_gic[DROWS*768];
__device__ __align__(16) float g_gia[DROWS*768];
__device__ __align__(16) float g_hq[2][QN*HID];
__device__ __align__(16) float g_hc[2][DN*HID];
__device__ __align__(16) float g_ha[2][DN*HID];
__device__ __align__(16) float g_cfin[DN*HID];
__device__ unsigned g_bar[3*64];

// ---------------- K0: embedding gather -------------------------------------
__global__ void gather_k(const int* __restrict__ qt, const int* __restrict__ pt,
                         const int* __restrict__ nt,
                         const float* __restrict__ temb, const float* __restrict__ demb) {
    int row = blockIdx.x;
    const float4* src; float4* dst;
    if (row < QROWS) {
        src = (const float4*)(temb + (size_t)qt[row]*HID);
        dst = (float4*)(g_xq + (size_t)row*HID);
    } else {
        int r = row - QROWS;
        int tok = (r < 600) ? pt[r] : nt[r-600];
        src = (const float4*)(demb + (size_t)tok*HID);
        dst = (float4*)(g_xd + (size_t)r*HID);
    }
    dst[threadIdx.x] = src[threadIdx.x];   // 64 threads x float4 = 256 floats
}

// ---------------- K1: gi = X @ W^T + b (three segments) --------------------
#define BM 64
#define BN 64
#define BK 32

__global__ void __launch_bounds__(256) gi_gemm_k(
    const float* __restrict__ tW, const float* __restrict__ tb,
    const float* __restrict__ cW, const float* __restrict__ cb,
    const float* __restrict__ aW, const float* __restrict__ ab) {
    const int NT = 768/BN;          // 12
    const int mt0 = QROWS/BM;       // 20
    const int mt1 = (DROWS+BM-1)/BM;// 19
    int bid = blockIdx.x;
    const float* X; const float* W; const float* bias; float* C; int M; int mtile;
    if (bid < mt0*NT)               { X=g_xq; W=tW; bias=tb; C=g_giq; M=QROWS; mtile=bid/NT; }
    else if (bid < (mt0+mt1)*NT)    { int b=bid-mt0*NT;        X=g_xd; W=cW; bias=cb; C=g_gic; M=DROWS; mtile=b/NT; }
    else                            { int b=bid-(mt0+mt1)*NT;  X=g_xd; W=aW; bias=ab; C=g_gia; M=DROWS; mtile=b/NT; }
    int ntile = bid % NT;
    int m0 = mtile*BM, n0 = ntile*BN;

    __shared__ float As[BK][BM+4];
    __shared__ float Bs[BK][BN+4];
    int tid = threadIdx.x;
    int tx = tid & 15, ty = tid >> 4;
    float acc[4][4] = {};

    for (int k0 = 0; k0 < HID; k0 += BK) {
        #pragma unroll
        for (int i = 0; i < 2; i++) {
            int idx = tid*2 + i;          // 0..511
            int m  = idx >> 3;
            int kk = (idx & 7) << 2;
            float4 v = make_float4(0.f,0.f,0.f,0.f);
            if (m0+m < M) v = *(const float4*)(X + (size_t)(m0+m)*HID + k0 + kk);
            As[kk+0][m]=v.x; As[kk+1][m]=v.y; As[kk+2][m]=v.z; As[kk+3][m]=v.w;
        }
        #pragma unroll
        for (int i = 0; i < 2; i++) {
            int idx = tid*2 + i;
            int n  = idx >> 3;
            int kk = (idx & 7) << 2;
            float4 v = *(const float4*)(W + (size_t)(n0+n)*HID + k0 + kk);
            Bs[kk+0][n]=v.x; Bs[kk+1][n]=v.y; Bs[kk+2][n]=v.z; Bs[kk+3][n]=v.w;
        }
        __syncthreads();
        #pragma unroll
        for (int k = 0; k < BK; k++) {
            float a[4], b[4];
            #pragma unroll
            for (int i=0;i<4;i++) a[i] = As[k][ty*4+i];
            #pragma unroll
            for (int j=0;j<4;j++) b[j] = Bs[k][tx*4+j];
            #pragma unroll
            for (int i=0;i<4;i++)
                #pragma unroll
                for (int j=0;j<4;j++) acc[i][j] = fmaf(a[i], b[j], acc[i][j]);
        }
        __syncthreads();
    }
    #pragma unroll
    for (int i=0;i<4;i++) {
        int m = m0 + ty*4 + i;
        if (m >= M) continue;
        int n = n0 + tx*4;
        float4 o;
        o.x = acc[i][0] + bias[n+0];
        o.y = acc[i][1] + bias[n+1];
        o.z = acc[i][2] + bias[n+2];
        o.w = acc[i][3] + bias[n+3];
        *(float4*)(C + (size_t)m*768 + n) = o;
    }
}

// ---------------- K2: three concurrent GRU scans with per-step barriers ----
#define NC_C 54
#define NC_A 54
#define NC_Q 40
#define SCAN_THREADS 384

__device__ __forceinline__ void bar_arrive_wait(unsigned* p, unsigned need) {
    asm volatile("red.release.gpu.global.add.u32 [%0], %1;" :: "l"(p), "r"(1u) : "memory");
    unsigned v;
    do {
        asm volatile("ld.acquire.gpu.global.u32 %0, [%1];" : "=r"(v) : "l"(p) : "memory");
    } while (v < need);
}

__global__ void __launch_bounds__(SCAN_THREADS) scan_k(
    const float* __restrict__ tWhh, const float* __restrict__ tbhh,
    const float* __restrict__ cWhh, const float* __restrict__ cbhh,
    const float* __restrict__ aWhh, const float* __restrict__ abhh) {
    extern __shared__ float sm[];
    int bid = blockIdx.x;
    int local, NC, B, T, KS;
    const float* Whh; const float* bhh; const float* gi;
    float* hbuf0; float* hbuf1; unsigned* bar;
    if (bid < NC_C) {
        local=bid; NC=NC_C; B=DN; T=LD; KS=4;
        Whh=cWhh; bhh=cbhh; gi=g_gic; hbuf0=g_hc[0]; hbuf1=g_hc[1]; bar=g_bar;
    } else if (bid < NC_C+NC_A) {
        local=bid-NC_C; NC=NC_A; B=DN; T=LD; KS=4;
        Whh=aWhh; bhh=abhh; gi=g_gia; hbuf0=g_ha[0]; hbuf1=g_ha[1]; bar=g_bar+64;
    } else {
        local=bid-NC_C-NC_A; NC=NC_Q; B=QN; T=LQ; KS=1;
        Whh=tWhh; bhh=tbhh; gi=g_giq; hbuf0=g_hq[0]; hbuf1=g_hq[1]; bar=g_bar+128;
    }
    int c0 = local*256/NC, c1 = (local+1)*256/NC;
    int HC = c1 - c0, G = 3*HC;
    int tid = threadIdx.x;

    float* h_s  = sm;              // B*256
    float* W_s  = sm + B*256;      // G*256
    float* part = W_s + G*256;     // B*G*KS

    // stage the Whh slice (rows for our gate columns) into smem once
    for (int idx = tid; idx < G*64; idx += SCAN_THREADS) {
        int g = idx >> 6, kk = (idx & 63) << 2;
        int grow = (g/HC)*256 + c0 + (g - (g/HC)*HC);
        *(float4*)(W_s + g*256 + kk) = *(const float4*)(Whh + (size_t)grow*HID + kk);
    }
    // h0 = 0
    for (int idx = tid; idx < B*64; idx += SCAN_THREADS)
        ((float4*)h_s)[idx] = make_float4(0.f,0.f,0.f,0.f);
    __syncthreads();

    int Btiles = B/2;
    int Gtiles = (G+1)/2;
    int L = 256/KS;
    int nthr = Btiles*Gtiles*KS;
    bool active = tid < nthr;
    int ks=0, b0=0, g0=0; bool g1v=false;
    if (active) {
        ks = tid % KS; int t2 = tid / KS;
        g0 = (t2 % Gtiles)*2; b0 = (t2 / Gtiles)*2;
        g1v = (g0+1 < G);
    }
    int kbeg = ks*L;

    for (int t = 0; t < T; t++) {
        if (active) {
            float a00=0.f,a01=0.f,a10=0.f,a11=0.f;
            const float4* h0p = (const float4*)(h_s + b0*256 + kbeg);
            const float4* h1p = (const float4*)(h_s + (b0+1)*256 + kbeg);
            const float4* w0p = (const float4*)(W_s + g0*256 + kbeg);
            const float4* w1p = (const float4*)(W_s + (g1v? g0+1 : g0)*256 + kbeg);
            #pragma unroll 8
            for (int kk = 0; kk < L/4; kk++) {
                float4 h0 = h0p[kk], h1 = h1p[kk], w0 = w0p[kk], w1 = w1p[kk];
                a00 = fmaf(h0.x,w0.x,a00); a00 = fmaf(h0.y,w0.y,a00);
                a00 = fmaf(h0.z,w0.z,a00); a00 = fmaf(h0.w,w0.w,a00);
                a01 = fmaf(h0.x,w1.x,a01); a01 = fmaf(h0.y,w1.y,a01);
                a01 = fmaf(h0.z,w1.z,a01); a01 = fmaf(h0.w,w1.w,a01);
                a10 = fmaf(h1.x,w0.x,a10); a10 = fmaf(h1.y,w0.y,a10);
                a10 = fmaf(h1.z,w0.z,a10); a10 = fmaf(h1.w,w0.w,a10);
                a11 = fmaf(h1.x,w1.x,a11); a11 = fmaf(h1.y,w1.y,a11);
                a11 = fmaf(h1.z,w1.z,a11); a11 = fmaf(h1.w,w1.w,a11);
            }
            part[(b0*G + g0)*KS + ks] = a00;
            part[((b0+1)*G + g0)*KS + ks] = a10;
            if (g1v) {
                part[(b0*G + g0+1)*KS + ks] = a01;
                part[((b0+1)*G + g0+1)*KS + ks] = a11;
            }
        }
        __syncthreads();
        // reduce over K-splits, gate math, write h_next to global
        float* hdst = ((t+1)&1) ? hbuf1 : hbuf0;
        for (int idx = tid; idx < B*HC; idx += SCAN_THREADS) {
            int b = idx / HC, j = idx - (idx/HC)*HC;
            int c = c0 + j;
            float ghr = bhh[c], ghz = bhh[256+c], ghn = bhh[512+c];
            #pragma unroll
            for (int s = 0; s < 4; s++) {
                if (s < KS) {
                    ghr += part[(b*G + j)*KS + s];
                    ghz += part[(b*G + HC+j)*KS + s];
                    ghn += part[(b*G + 2*HC+j)*KS + s];
                }
            }
            const float* gip = gi + ((size_t)b*T + t)*768;
            float r = 1.f/(1.f + expf(-(gip[c]     + ghr)));
            float z = 1.f/(1.f + expf(-(gip[256+c] + ghz)));
            float n = tanhf(gip[512+c] + r*ghn);
            hdst[b*256 + c] = (1.f - z)*n + z*h_s[b*256 + c];
        }
        __threadfence();
        __syncthreads();
        if (tid == 0) bar_arrive_wait(bar + t, (unsigned)NC);
        __syncthreads();
        if (t+1 < T) {
            const float* hsrc = ((t+1)&1) ? hbuf1 : hbuf0;
            for (int idx = tid; idx < B*64; idx += SCAN_THREADS)
                ((float4*)h_s)[idx] = ((const float4*)hsrc)[idx];
            __syncthreads();
        }
    }
}

// ---------------- K3a: position dense on content vectors -------------------
__global__ void posdense_k(const float* __restrict__ posW, const float* __restrict__ posb,
                           const float* __restrict__ ptab) {
    __shared__ float hs[256];
    __shared__ float pe[4];
    int d = blockIdx.x, j = threadIdx.x;
    hs[j] = g_hc[0][d*256 + j];
    if (j < 4) pe[j] = ptab[(d%12)*4 + j];
    __syncthreads();
    const float* wr = posW + (size_t)j*260;
    float acc = posb[j];
    #pragma unroll 8
    for (int k = 0; k < 256; k += 4) {
        float4 w = *(const float4*)(wr + k);
        acc = fmaf(hs[k],   w.x, acc);
        acc = fmaf(hs[k+1], w.y, acc);
        acc = fmaf(hs[k+2], w.z, acc);
        acc = fmaf(hs[k+3], w.w, acc);
    }
    float4 wp = *(const float4*)(wr + 256);
    acc = fmaf(pe[0],wp.x, fmaf(pe[1],wp.y, fmaf(pe[2],wp.z, fmaf(pe[3],wp.w, acc))));
    g_cfin[d*256 + j] = acc;
}

// ---------------- K3b: attention + final GRU step (h0 = 0) -----------------
__global__ void final_k(const float* __restrict__ qWih, const float* __restrict__ qbih,
                        const float* __restrict__ qbhh, float* __restrict__ out) {
    __shared__ float enc[256];
    __shared__ float wgt[24];
    __shared__ float qpn[256];
    __shared__ float gi2[768];
    int q = blockIdx.x, tid = threadIdx.x;
    enc[tid] = g_hq[0][q*256 + tid];
    __syncthreads();
    if (tid < 24) {
        const float* ar = g_ha[0] + tid*256;
        float s = 0.f;
        #pragma unroll 8
        for (int k = 0; k < 256; k += 4) {
            float4 a = *(const float4*)(ar + k);
            s = fmaf(enc[k],a.x,s); s = fmaf(enc[k+1],a.y,s);
            s = fmaf(enc[k+2],a.z,s); s = fmaf(enc[k+3],a.w,s);
        }
        wgt[tid] = s;
    }
    __syncthreads();
    if (tid < 2) {
        int off = tid*12;
        float mx = -1e30f;
        for (int d=0; d<12; d++) mx = fmaxf(mx, wgt[off+d]);
        float sum = 0.f;
        for (int d=0; d<12; d++) { float e = expf(wgt[off+d]-mx); wgt[off+d]=e; sum += e; }
        float inv = 1.f/sum;
        for (int d=0; d<12; d++) wgt[off+d] *= inv;
    }
    __syncthreads();
    float v = enc[tid];
    #pragma unroll
    for (int d=0; d<24; d++) v = fmaf(wgt[d], g_cfin[d*256 + tid], v);
    qpn[tid] = v;
    __syncthreads();
    for (int g = tid; g < 768; g += 256) {
        const float* wr = qWih + (size_t)g*256;
        float acc = qbih[g];
        #pragma unroll 8
        for (int k = 0; k < 256; k += 4) {
            float4 w = *(const float4*)(wr + k);
            acc = fmaf(qpn[k],w.x,acc); acc = fmaf(qpn[k+1],w.y,acc);
            acc = fmaf(qpn[k+2],w.z,acc); acc = fmaf(qpn[k+3],w.w,acc);
        }
        gi2[g] = acc;
    }
    __syncthreads();
    float r = 1.f/(1.f + expf(-(gi2[tid]     + qbhh[tid])));
    float z = 1.f/(1.f + expf(-(gi2[256+tid] + qbhh[256+tid])));
    float n = tanhf(gi2[512+tid] + r*qbhh[512+tid]);
    out[q*256 + tid] = (1.f - z)*n;
}

// ---------------- launch ----------------------------------------------------
extern "C" void kernel_launch(void* const* d_in, const int* in_sizes, int n_in,
                              void* d_out, int out_size) {
    const int*   qt   = (const int*)d_in[0];
    const int*   pt   = (const int*)d_in[1];
    const int*   nt   = (const int*)d_in[2];
    const float* temb = (const float*)d_in[3];
    const float* tWih = (const float*)d_in[4];
    const float* tWhh = (const float*)d_in[5];
    const float* tbih = (const float*)d_in[6];
    const float* tbhh = (const float*)d_in[7];
    const float* demb = (const float*)d_in[8];
    const float* cWih = (const float*)d_in[9];
    const float* cWhh = (const float*)d_in[10];
    const float* cbih = (const float*)d_in[11];
    const float* cbhh = (const float*)d_in[12];
    const float* aWih = (const float*)d_in[13];
    const float* aWhh = (const float*)d_in[14];
    const float* abih = (const float*)d_in[15];
    const float* abhh = (const float*)d_in[16];
    const float* ptab = (const float*)d_in[17];
    const float* posW = (const float*)d_in[18];
    const float* posb = (const float*)d_in[19];
    const float* qWih = (const float*)d_in[20];
    const float* qbih = (const float*)d_in[22];
    const float* qbhh = (const float*)d_in[23];

    // zero per-step barrier counters (memset node in the graph each replay)
    void* barp = nullptr;
    cudaGetSymbolAddress(&barp, g_bar);
    cudaMemsetAsync(barp, 0, sizeof(unsigned)*3*64);

    gather_k<<<QROWS + DROWS, 64>>>(qt, pt, nt, temb, demb);

    const int NT = 768/BN;
    int nblk = (QROWS/BM)*NT + 2*((DROWS+BM-1)/BM)*NT;   // 240 + 456 = 696
    gi_gemm_k<<<nblk, 256>>>(tWih, tbih, cWih, cbih, aWih, abih);

    // scan smem: max over chains of (B*256 + G*256 + B*G*KS)*4 bytes
    // q-chain: (64*256 + 21*256 + 64*21)*4 = 92416
    int scan_smem = 92416;
    cudaFuncSetAttribute(scan_k, cudaFuncAttributeMaxDynamicSharedMemorySize, scan_smem);
    scan_k<<<NC_C + NC_A + NC_Q, SCAN_THREADS, scan_smem>>>(tWhh, tbhh, cWhh, cbhh, aWhh, abhh);

    posdense_k<<<DN, 256>>>(posW, posb, ptab);
    final_k<<<QN, 256>>>(qWih, qbih, qbhh, (float*)d_out);
}